// round 4
// baseline (speedup 1.0000x reference)
#include <cuda_runtime.h>
#include <cstdint>

#define N_NODES 100000
#define N_EDGES 1600000
#define D_FEAT  128
#define N_POOL  25000
#define D4      (D_FEAT / 4)   // 32 float4 per row -> one warp per row

// Scratch (allocation is forbidden; __device__ globals are the sanctioned path)
__device__ float g_Y[(size_t)N_NODES * D_FEAT];  // hop-1 result: x + agg1
__device__ float g_Z[(size_t)N_NODES * D_FEAT];  // hop-2 aggregate

// ---------------------------------------------------------------------------
// 1) Y = x, Z = 0   (float4-vectorized)
// ---------------------------------------------------------------------------
__global__ void init_kernel(const float* __restrict__ x) {
    int i = blockIdx.x * blockDim.x + threadIdx.x;
    const int n4 = N_NODES * D4;
    if (i < n4) {
        const float4* x4 = reinterpret_cast<const float4*>(x);
        float4* y4 = reinterpret_cast<float4*>(g_Y);
        float4* z4 = reinterpret_cast<float4*>(g_Z);
        y4[i] = x4[i];
        z4[i] = make_float4(0.f, 0.f, 0.f, 0.f);
    }
}

// ---------------------------------------------------------------------------
// 2) scatter hop: acc[dst] += xin[src] * w   — one warp per edge,
//    one float4 per lane, L2-side no-return vector reduction.
//    Indices are int32 (JAX silently downcasts int64 without x64 mode).
// ---------------------------------------------------------------------------
__global__ void __launch_bounds__(256) scatter_kernel(
    const float* __restrict__ xin,
    const float* __restrict__ edge_attr,
    const int* __restrict__ src,
    const int* __restrict__ dst,
    float* __restrict__ acc)
{
    int warp = (blockIdx.x * blockDim.x + threadIdx.x) >> 5;
    int lane = threadIdx.x & 31;
    if (warp >= N_EDGES) return;

    int   s = __ldg(src + warp);
    int   d = __ldg(dst + warp);
    float w = __ldg(edge_attr + warp);

    const float4* row = reinterpret_cast<const float4*>(xin + (size_t)s * D_FEAT);
    float4 v = __ldg(row + lane);
    v.x *= w; v.y *= w; v.z *= w; v.w *= w;

    float* p = acc + (size_t)d * D_FEAT + lane * 4;
    asm volatile("red.global.add.v4.f32 [%0], {%1,%2,%3,%4};"
                 :: "l"(p), "f"(v.x), "f"(v.y), "f"(v.z), "f"(v.w)
                 : "memory");
}

// ---------------------------------------------------------------------------
// 3) out[i] = Y[sel[i]] + Z[sel[i]]   — one warp per output row
// ---------------------------------------------------------------------------
__global__ void __launch_bounds__(256) gather_kernel(
    const int* __restrict__ sel,
    float* __restrict__ out)
{
    int row  = (blockIdx.x * blockDim.x + threadIdx.x) >> 5;
    int lane = threadIdx.x & 31;
    if (row >= N_POOL) return;

    int s = __ldg(sel + row);
    const float4* y4 = reinterpret_cast<const float4*>(g_Y + (size_t)s * D_FEAT);
    const float4* z4 = reinterpret_cast<const float4*>(g_Z + (size_t)s * D_FEAT);
    float4 a = __ldg(y4 + lane);
    float4 b = __ldg(z4 + lane);
    a.x += b.x; a.y += b.y; a.z += b.z; a.w += b.w;
    reinterpret_cast<float4*>(out + (size_t)row * D_FEAT)[lane] = a;
}

// ---------------------------------------------------------------------------
extern "C" void kernel_launch(void* const* d_in, const int* in_sizes, int n_in,
                              void* d_out, int out_size)
{
    const float* x    = (const float*)d_in[0];   // [N, 128] f32
    const float* ea   = (const float*)d_in[1];   // [E] f32
    const int*   eidx = (const int*)d_in[2];     // [2, E] int32 (JAX x64-off)
    const int*   sel  = (const int*)d_in[3];     // [N_pool] int32
    float* out = (float*)d_out;

    const int* src = eidx;            // row 0 (x_j sources)
    const int* dst = eidx + N_EDGES;  // row 1 (aggregation targets)

    float* Y; float* Z;
    cudaGetSymbolAddress((void**)&Y, g_Y);
    cudaGetSymbolAddress((void**)&Z, g_Z);

    // 1) Y = x, Z = 0
    {
        int n4 = N_NODES * D4;
        init_kernel<<<(n4 + 255) / 256, 256>>>(x);
    }
    // 2) hop 1: Y += x[src] * w   (Y pre-seeded with x -> residual is free)
    {
        int warps_per_block = 256 / 32;
        int blocks = (N_EDGES + warps_per_block - 1) / warps_per_block;
        scatter_kernel<<<blocks, 256>>>(x, ea, src, dst, Y);
    }
    // 3) hop 2: Z += Y[src] * w
    {
        int warps_per_block = 256 / 32;
        int blocks = (N_EDGES + warps_per_block - 1) / warps_per_block;
        scatter_kernel<<<blocks, 256>>>(Y, ea, src, dst, Z);
    }
    // 4) out = Y[sel] + Z[sel]
    {
        int rows_per_block = 256 / 32;
        int blocks = (N_POOL + rows_per_block - 1) / rows_per_block;
        gather_kernel<<<blocks, 256>>>(sel, out);
    }
}

// round 5
// speedup vs baseline: 2.5640x; 2.5640x over previous
#include <cuda_runtime.h>
#include <cstdint>

#define N_NODES 100000
#define N_EDGES 1600000
#define D_FEAT  128
#define N_POOL  25000
#define D4      (D_FEAT / 4)          // 32 float4 per row -> one warp per row
#define SCAN_B  1024
#define NBLK    ((N_NODES + SCAN_B - 1) / SCAN_B)   // 98

// ---- scratch (__device__ globals; allocation is forbidden) ----------------
__device__ float g_Y[(size_t)N_NODES * D_FEAT];   // hop-1 result: x + agg1
__device__ float g_Z[(size_t)N_NODES * D_FEAT];   // hop-2 result at flagged nodes
__device__ int   g_cnt[N_NODES];                  // in-degree histogram
__device__ int   g_off[N_NODES];                  // CSR row offsets (exclusive)
__device__ int   g_cur[N_NODES];                  // write cursors for reorder
__device__ int   g_bsum[NBLK];                    // scan block sums
__device__ int   g_esrc[N_EDGES];                 // edges sorted by dst: src id
__device__ float g_ew[N_EDGES];                   //                      weight
__device__ unsigned char g_flag[N_NODES];         // node appears in sel_idx

// ---------------------------------------------------------------------------
__global__ void clear_kernel() {
    int i = blockIdx.x * blockDim.x + threadIdx.x;
    if (i < N_NODES) { g_cnt[i] = 0; g_flag[i] = 0; }
}

__global__ void flag_kernel(const int* __restrict__ sel) {
    int i = blockIdx.x * blockDim.x + threadIdx.x;
    if (i < N_POOL) g_flag[sel[i]] = 1;
}

__global__ void hist_kernel(const int* __restrict__ dst) {
    int i = blockIdx.x * blockDim.x + threadIdx.x;
    if (i < N_EDGES) atomicAdd(&g_cnt[dst[i]], 1);
}

// Block-level exclusive scan (Hillis-Steele inclusive, then subtract own)
__global__ void __launch_bounds__(SCAN_B) scan1_kernel() {
    __shared__ int sh[SCAN_B];
    int i = blockIdx.x * SCAN_B + threadIdx.x;
    int v = (i < N_NODES) ? g_cnt[i] : 0;
    sh[threadIdx.x] = v;
    __syncthreads();
    for (int d = 1; d < SCAN_B; d <<= 1) {
        int t = (threadIdx.x >= d) ? sh[threadIdx.x - d] : 0;
        __syncthreads();
        sh[threadIdx.x] += t;
        __syncthreads();
    }
    if (i < N_NODES) g_off[i] = sh[threadIdx.x] - v;
    if (threadIdx.x == SCAN_B - 1) g_bsum[blockIdx.x] = sh[SCAN_B - 1];
}

__global__ void scan2_kernel() {   // tiny serial scan over 98 block sums
    if (threadIdx.x == 0) {
        int acc = 0;
        for (int i = 0; i < NBLK; i++) { int t = g_bsum[i]; g_bsum[i] = acc; acc += t; }
    }
}

__global__ void scan3_kernel() {
    int i = blockIdx.x * blockDim.x + threadIdx.x;
    if (i < N_NODES) {
        int o = g_off[i] + g_bsum[i / SCAN_B];
        g_off[i] = o;
        g_cur[i] = o;
    }
}

__global__ void reorder_kernel(const int* __restrict__ src,
                               const int* __restrict__ dst,
                               const float* __restrict__ ea) {
    int i = blockIdx.x * blockDim.x + threadIdx.x;
    if (i < N_EDGES) {
        int d   = dst[i];
        int pos = atomicAdd(&g_cur[d], 1);
        g_esrc[pos] = src[i];
        g_ew[pos]   = ea[i];
    }
}

// ---------------------------------------------------------------------------
// Gather-style hop: one warp per dst node, one float4 per lane.
//   out[n] = base[n] + sum_{e in CSR(n)} xin[esrc[e]] * ew[e]
// FLAGGED=true restricts work to nodes present in sel_idx (hop 2).
// ---------------------------------------------------------------------------
template <bool FLAGGED>
__global__ void __launch_bounds__(256) hop_kernel(
    const float4* __restrict__ xin4,    // source features (gathered)
    const float4* __restrict__ base4,   // residual seed
    float4* __restrict__ out4)
{
    int n    = (blockIdx.x * blockDim.x + threadIdx.x) >> 5;
    int lane = threadIdx.x & 31;
    if (n >= N_NODES) return;
    if (FLAGGED && !g_flag[n]) return;

    float4 acc = __ldg(&base4[(size_t)n * D4 + lane]);

    int s0 = __ldg(&g_off[n]);
    int c  = __ldg(&g_cnt[n]);

    for (int b = 0; b < c; b += 32) {
        int idx = b + lane;
        int   s = 0;
        float w = 0.f;
        if (idx < c) {
            s = __ldg(g_esrc + s0 + idx);
            w = __ldg(g_ew   + s0 + idx);
        }
        int m = min(32, c - b);
        #pragma unroll 4
        for (int j = 0; j < m; ++j) {
            int   ss = __shfl_sync(0xffffffffu, s, j);
            float ww = __shfl_sync(0xffffffffu, w, j);
            float4 v = __ldg(&xin4[(size_t)ss * D4 + lane]);
            acc.x += v.x * ww;
            acc.y += v.y * ww;
            acc.z += v.z * ww;
            acc.w += v.w * ww;
        }
    }
    out4[(size_t)n * D4 + lane] = acc;
}

// ---------------------------------------------------------------------------
__global__ void __launch_bounds__(256) gather_kernel(
    const int* __restrict__ sel, float4* __restrict__ out4)
{
    int row  = (blockIdx.x * blockDim.x + threadIdx.x) >> 5;
    int lane = threadIdx.x & 31;
    if (row >= N_POOL) return;
    int s = __ldg(sel + row);
    const float4* z4 = reinterpret_cast<const float4*>(g_Z);
    out4[(size_t)row * D4 + lane] = __ldg(&z4[(size_t)s * D4 + lane]);
}

// ---------------------------------------------------------------------------
extern "C" void kernel_launch(void* const* d_in, const int* in_sizes, int n_in,
                              void* d_out, int out_size)
{
    const float* x    = (const float*)d_in[0];   // [N, 128] f32
    const float* ea   = (const float*)d_in[1];   // [E] f32
    const int*   eidx = (const int*)d_in[2];     // [2, E] int32
    const int*   sel  = (const int*)d_in[3];     // [N_pool] int32
    float* out = (float*)d_out;

    const int* src = eidx;            // row 0 (x_j sources)
    const int* dst = eidx + N_EDGES;  // row 1 (aggregation targets)

    float* Y; float* Z;
    cudaGetSymbolAddress((void**)&Y, g_Y);
    cudaGetSymbolAddress((void**)&Z, g_Z);
    const float4* x4 = reinterpret_cast<const float4*>(x);
    float4* Y4 = reinterpret_cast<float4*>(Y);
    float4* Z4 = reinterpret_cast<float4*>(Z);

    const int TB = 256;

    // CSR build (by dst) + selection flags
    clear_kernel<<<(N_NODES + TB - 1) / TB, TB>>>();
    hist_kernel<<<(N_EDGES + TB - 1) / TB, TB>>>(dst);
    flag_kernel<<<(N_POOL + TB - 1) / TB, TB>>>(sel);
    scan1_kernel<<<NBLK, SCAN_B>>>();
    scan2_kernel<<<1, 32>>>();
    scan3_kernel<<<(N_NODES + TB - 1) / TB, TB>>>();
    reorder_kernel<<<(N_EDGES + TB - 1) / TB, TB>>>(src, dst, ea);

    // hop 1 (all nodes):      Y = x + A@x
    {
        int blocks = (N_NODES * 32 + TB - 1) / TB;
        hop_kernel<false><<<blocks, TB>>>(x4, x4, Y4);
    }
    // hop 2 (flagged only):   Z = Y + A@Y   (only rows read by sel)
    {
        int blocks = (N_NODES * 32 + TB - 1) / TB;
        hop_kernel<true><<<blocks, TB>>>(
            (const float4*)Y4, (const float4*)Y4, Z4);
    }
    // out = Z[sel]
    {
        int blocks = (N_POOL * 32 + TB - 1) / TB;
        gather_kernel<<<blocks, TB>>>(sel, (float4*)out);
    }
}

// round 6
// speedup vs baseline: 2.8047x; 1.0939x over previous
#include <cuda_runtime.h>
#include <cstdint>

#define N_NODES 100000
#define N_EDGES 1600000
#define D_FEAT  128
#define N_POOL  25000
#define D4      (D_FEAT / 4)          // 32 float4 per row -> one warp per row
#define SCAN_B  1024
#define NBLK    ((N_NODES + SCAN_B - 1) / SCAN_B)   // 98

// ---- scratch (__device__ globals; allocation is forbidden) ----------------
__device__ float g_Y[(size_t)N_NODES * D_FEAT];   // hop-1 result: x + agg1
__device__ float g_Z[(size_t)N_NODES * D_FEAT];   // hop-2 result at flagged nodes
__device__ int   g_cnt[N_NODES];                  // in-degree histogram
__device__ int   g_off[N_NODES];                  // CSR row offsets (exclusive)
__device__ int   g_cur[N_NODES];                  // write cursors for reorder
__device__ int   g_bsum[NBLK];                    // scan block sums
__device__ int2  g_epack[N_EDGES];                // (src, weight-bits) by dst
__device__ unsigned char g_flag[N_NODES];         // node appears in sel_idx

// ---------------------------------------------------------------------------
__global__ void clear_kernel() {
    int i = blockIdx.x * blockDim.x + threadIdx.x;
    if (i < N_NODES) { g_cnt[i] = 0; g_flag[i] = 0; }
}

__global__ void flag_kernel(const int* __restrict__ sel) {
    int i = blockIdx.x * blockDim.x + threadIdx.x;
    if (i < N_POOL) g_flag[sel[i]] = 1;
}

__global__ void hist_kernel(const int* __restrict__ dst) {
    int i = blockIdx.x * blockDim.x + threadIdx.x;
    if (i < N_EDGES) atomicAdd(&g_cnt[dst[i]], 1);
}

// Two-level shfl block scan: per-warp inclusive scan, warp sums scanned by
// warp 0, add back. 2 barriers instead of 20.
__global__ void __launch_bounds__(SCAN_B) scan1_kernel() {
    __shared__ int wsum[32];
    int i = blockIdx.x * SCAN_B + threadIdx.x;
    int v = (i < N_NODES) ? g_cnt[i] : 0;
    int lane = threadIdx.x & 31, w = threadIdx.x >> 5;
    int s = v;
    #pragma unroll
    for (int d = 1; d < 32; d <<= 1) {
        int u = __shfl_up_sync(0xffffffffu, s, d);
        if (lane >= d) s += u;
    }
    if (lane == 31) wsum[w] = s;
    __syncthreads();
    if (w == 0) {
        int ws = wsum[lane];
        #pragma unroll
        for (int d = 1; d < 32; d <<= 1) {
            int u = __shfl_up_sync(0xffffffffu, ws, d);
            if (lane >= d) ws += u;
        }
        wsum[lane] = ws;
    }
    __syncthreads();
    int incl = s + (w > 0 ? wsum[w - 1] : 0);
    if (i < N_NODES) g_off[i] = incl - v;          // exclusive within block
    if (threadIdx.x == SCAN_B - 1) g_bsum[blockIdx.x] = incl;
}

// Parallel warp scan over the 98 block sums (replaces serial 1-thread loop,
// whose dependent L2 load/store chain cost ~25us).
__global__ void scan2_kernel() {
    __shared__ int wsum[4];
    int t = threadIdx.x;                // 128 threads
    int v = (t < NBLK) ? g_bsum[t] : 0;
    int lane = t & 31, w = t >> 5;
    int s = v;
    #pragma unroll
    for (int d = 1; d < 32; d <<= 1) {
        int u = __shfl_up_sync(0xffffffffu, s, d);
        if (lane >= d) s += u;
    }
    if (lane == 31) wsum[w] = s;
    __syncthreads();
    if (w == 0 && lane < 4) {
        int ws = wsum[lane];
        #pragma unroll
        for (int d = 1; d < 4; d <<= 1) {
            int u = __shfl_up_sync(0xfu, ws, d);
            if (lane >= d) ws += u;
        }
        wsum[lane] = ws;
    }
    __syncthreads();
    int incl = s + (w > 0 ? wsum[w - 1] : 0);
    if (t < NBLK) g_bsum[t] = incl - v;            // exclusive
}

__global__ void scan3_kernel() {
    int i = blockIdx.x * blockDim.x + threadIdx.x;
    if (i < N_NODES) {
        int o = g_off[i] + g_bsum[i / SCAN_B];
        g_off[i] = o;
        g_cur[i] = o;
    }
}

__global__ void reorder_kernel(const int* __restrict__ src,
                               const int* __restrict__ dst,
                               const float* __restrict__ ea) {
    int i = blockIdx.x * blockDim.x + threadIdx.x;
    if (i < N_EDGES) {
        int d   = dst[i];
        int pos = atomicAdd(&g_cur[d], 1);
        g_epack[pos] = make_int2(src[i], __float_as_int(ea[i]));  // one 8B store
    }
}

// ---------------------------------------------------------------------------
// Gather-style hop: one warp per dst node, one float4 per lane.
//   out[n] = base[n] + sum_{e in CSR(n)} xin[epack[e].src] * epack[e].w
// FLAGGED=true restricts work to nodes present in sel_idx (hop 2).
// ---------------------------------------------------------------------------
template <bool FLAGGED>
__global__ void __launch_bounds__(256) hop_kernel(
    const float4* __restrict__ xin4,    // source features (gathered)
    const float4* __restrict__ base4,   // residual seed
    float4* __restrict__ out4)
{
    int n    = (blockIdx.x * blockDim.x + threadIdx.x) >> 5;
    int lane = threadIdx.x & 31;
    if (n >= N_NODES) return;
    if (FLAGGED && !g_flag[n]) return;

    float4 acc = __ldg(&base4[(size_t)n * D4 + lane]);

    int s0 = __ldg(&g_off[n]);
    int c  = __ldg(&g_cnt[n]);

    for (int b = 0; b < c; b += 32) {
        int idx = b + lane;
        int   s = 0;
        float w = 0.f;
        if (idx < c) {
            int2 e = __ldg(&g_epack[s0 + idx]);
            s = e.x;
            w = __int_as_float(e.y);
        }
        int m = min(32, c - b);
        #pragma unroll 4
        for (int j = 0; j < m; ++j) {
            int   ss = __shfl_sync(0xffffffffu, s, j);
            float ww = __shfl_sync(0xffffffffu, w, j);
            float4 v = __ldg(&xin4[(size_t)ss * D4 + lane]);
            acc.x += v.x * ww;
            acc.y += v.y * ww;
            acc.z += v.z * ww;
            acc.w += v.w * ww;
        }
    }
    out4[(size_t)n * D4 + lane] = acc;
}

// ---------------------------------------------------------------------------
__global__ void __launch_bounds__(256) gather_kernel(
    const int* __restrict__ sel, float4* __restrict__ out4)
{
    int row  = (blockIdx.x * blockDim.x + threadIdx.x) >> 5;
    int lane = threadIdx.x & 31;
    if (row >= N_POOL) return;
    int s = __ldg(sel + row);
    const float4* z4 = reinterpret_cast<const float4*>(g_Z);
    out4[(size_t)row * D4 + lane] = __ldg(&z4[(size_t)s * D4 + lane]);
}

// ---------------------------------------------------------------------------
extern "C" void kernel_launch(void* const* d_in, const int* in_sizes, int n_in,
                              void* d_out, int out_size)
{
    const float* x    = (const float*)d_in[0];   // [N, 128] f32
    const float* ea   = (const float*)d_in[1];   // [E] f32
    const int*   eidx = (const int*)d_in[2];     // [2, E] int32
    const int*   sel  = (const int*)d_in[3];     // [N_pool] int32
    float* out = (float*)d_out;

    const int* src = eidx;            // row 0 (x_j sources)
    const int* dst = eidx + N_EDGES;  // row 1 (aggregation targets)

    float* Y; float* Z;
    cudaGetSymbolAddress((void**)&Y, g_Y);
    cudaGetSymbolAddress((void**)&Z, g_Z);
    const float4* x4 = reinterpret_cast<const float4*>(x);
    float4* Y4 = reinterpret_cast<float4*>(Y);
    float4* Z4 = reinterpret_cast<float4*>(Z);

    const int TB = 256;

    // CSR build (by dst) + selection flags
    clear_kernel<<<(N_NODES + TB - 1) / TB, TB>>>();
    hist_kernel<<<(N_EDGES + TB - 1) / TB, TB>>>(dst);
    flag_kernel<<<(N_POOL + TB - 1) / TB, TB>>>(sel);
    scan1_kernel<<<NBLK, SCAN_B>>>();
    scan2_kernel<<<1, 128>>>();
    scan3_kernel<<<(N_NODES + TB - 1) / TB, TB>>>();
    reorder_kernel<<<(N_EDGES + TB - 1) / TB, TB>>>(src, dst, ea);

    // hop 1 (all nodes):      Y = x + A@x
    {
        int blocks = (N_NODES * 32 + TB - 1) / TB;
        hop_kernel<false><<<blocks, TB>>>(x4, x4, Y4);
    }
    // hop 2 (flagged only):   Z = Y + A@Y   (only rows read by sel)
    {
        int blocks = (N_NODES * 32 + TB - 1) / TB;
        hop_kernel<true><<<blocks, TB>>>(
            (const float4*)Y4, (const float4*)Y4, Z4);
    }
    // out = Z[sel]
    {
        int blocks = (N_POOL * 32 + TB - 1) / TB;
        gather_kernel<<<blocks, TB>>>(sel, (float4*)out);
    }
}